// round 3
// baseline (speedup 1.0000x reference)
#include <cuda_runtime.h>

// Problem constants: x [B=8, C=64, H=64, W=64], N = H*W = 4096
#define BATCH 8
#define CDIM  64
#define NDIM  4096
#define NN    (NDIM * NDIM)          // 16,777,216 per batch
#define Y_ELEMS (BATCH * CDIM * NDIM) // 2,097,152

// ---------------------------------------------------------------------------
// Packed f32x2 helpers (Blackwell sm_103a): FFMA2 doubles fp32 FMA throughput.
// Only reachable via PTX fma.rn.f32x2 (ptxas never auto-fuses).
// ---------------------------------------------------------------------------
__device__ __forceinline__ unsigned long long pack2(float lo, float hi) {
    unsigned long long r;
    asm("mov.b64 %0, {%1, %2};" : "=l"(r) : "f"(lo), "f"(hi));
    return r;
}
__device__ __forceinline__ void unpack2(float& lo, float& hi, unsigned long long v) {
    asm("mov.b64 {%0, %1}, %2;" : "=f"(lo), "=f"(hi) : "l"(v));
}
__device__ __forceinline__ void ffma2(unsigned long long& d,
                                      unsigned long long a,
                                      unsigned long long b) {
    asm("fma.rn.f32x2 %0, %1, %2, %0;" : "+l"(d) : "l"(a), "l"(b));
}

// ---------------------------------------------------------------------------
// K1: raw scores  S[b][n][m] = sum_c x[b][c][n] * x[b][c][m]
// 128x128 output tile per CTA, K=64 in two smem chunks of 32.
// 256 threads (16x16); each thread: 8 rows (ty+16i) x 8 cols (pairs 2tx+32u).
// ---------------------------------------------------------------------------
__global__ __launch_bounds__(256, 2)
void scores_kernel(const float* __restrict__ x, float* __restrict__ attn) {
    __shared__ float Qs[32][128];
    __shared__ float Ks[32][128];

    const int t  = threadIdx.x;
    const int tx = t & 15;
    const int ty = t >> 4;
    const int m0 = blockIdx.x * 128;
    const int n0 = blockIdx.y * 128;
    const int b  = blockIdx.z;
    const float* xb = x + (size_t)b * (CDIM * NDIM);

    unsigned long long acc[8][4];
#pragma unroll
    for (int i = 0; i < 8; i++)
#pragma unroll
        for (int u = 0; u < 4; u++) acc[i][u] = 0ULL;  // (0.0f, 0.0f)

    for (int cc = 0; cc < CDIM; cc += 32) {
        // Load 32x128 chunks of Q (n-block) and K (m-block). Coalesced 512B rows.
#pragma unroll
        for (int k = 0; k < 16; k++) {
            int idx = t + k * 256;
            int cl  = idx >> 7;
            int j   = idx & 127;
            Qs[cl][j] = xb[(cc + cl) * NDIM + n0 + j];
            Ks[cl][j] = xb[(cc + cl) * NDIM + m0 + j];
        }
        __syncthreads();

#pragma unroll
        for (int cl = 0; cl < 32; cl++) {
            unsigned long long b2[4];
#pragma unroll
            for (int u = 0; u < 4; u++)  // lanes 8B apart -> conflict-free LDS.64
                b2[u] = *(const unsigned long long*)&Ks[cl][2 * tx + 32 * u];
#pragma unroll
            for (int i = 0; i < 8; i++) {
                float a = Qs[cl][ty + 16 * i];  // broadcast
                unsigned long long a2 = pack2(a, a);
#pragma unroll
                for (int u = 0; u < 4; u++) ffma2(acc[i][u], a2, b2[u]);
            }
        }
        __syncthreads();
    }

    // Write raw scores (overwritten in-place by softmax kernel).
    float* arow = attn + (size_t)b * NN;
#pragma unroll
    for (int i = 0; i < 8; i++) {
        size_t base = (size_t)(n0 + ty + 16 * i) * NDIM + m0;
#pragma unroll
        for (int u = 0; u < 4; u++) {
            float lo, hi;
            unpack2(lo, hi, acc[i][u]);
            *(float2*)&arow[base + 2 * tx + 32 * u] = make_float2(lo, hi);
        }
    }
}

// ---------------------------------------------------------------------------
// K2: in-place row softmax. One 128-thread block per (b, n) row.
// Row (4096 fp32 = 16KB) held entirely in registers (8 float4 per thread).
// ---------------------------------------------------------------------------
__global__ __launch_bounds__(128)
void softmax_kernel(float* __restrict__ attn) {
    const int n = blockIdx.x;
    const int b = blockIdx.y;
    float4* row = (float4*)(attn + (size_t)b * NN + (size_t)n * NDIM);
    const int t = threadIdx.x;

    float4 v[8];
    float m = -1e30f;
#pragma unroll
    for (int k = 0; k < 8; k++) {
        v[k] = row[t + 128 * k];
        m = fmaxf(m, fmaxf(fmaxf(v[k].x, v[k].y), fmaxf(v[k].z, v[k].w)));
    }
#pragma unroll
    for (int o = 16; o > 0; o >>= 1)
        m = fmaxf(m, __shfl_xor_sync(0xffffffffu, m, o));

    __shared__ float smax[4];
    __shared__ float ssum[4];
    const int warp = t >> 5, lane = t & 31;
    if (lane == 0) smax[warp] = m;
    __syncthreads();
    m = fmaxf(fmaxf(smax[0], smax[1]), fmaxf(smax[2], smax[3]));

    float s = 0.0f;
#pragma unroll
    for (int k = 0; k < 8; k++) {
        v[k].x = __expf(v[k].x - m);
        v[k].y = __expf(v[k].y - m);
        v[k].z = __expf(v[k].z - m);
        v[k].w = __expf(v[k].w - m);
        s += (v[k].x + v[k].y) + (v[k].z + v[k].w);
    }
#pragma unroll
    for (int o = 16; o > 0; o >>= 1)
        s += __shfl_xor_sync(0xffffffffu, s, o);
    if (lane == 0) ssum[warp] = s;
    __syncthreads();
    s = (ssum[0] + ssum[1]) + (ssum[2] + ssum[3]);

    const float inv = 1.0f / s;
#pragma unroll
    for (int k = 0; k < 8; k++) {
        v[k].x *= inv; v[k].y *= inv; v[k].z *= inv; v[k].w *= inv;
        row[t + 128 * k] = v[k];
    }
}

// ---------------------------------------------------------------------------
// K3: y[b][c][n] = sum_m attn[b][n][m] * x[b][c][m]
// CTA: 128 n-rows x all 64 c-cols; m streamed in chunks of 32.
// A tile stored transposed As[m][n] (pitch 130 -> 8B-aligned rows, odd bank
// step on writes); X tile Xs[m][c] (pitch 65 -> bank step 1).
// Thread: 4 row-PAIRS (f32x2 along n: 2ty+32i) x 4 cols (tx+16u).
// ---------------------------------------------------------------------------
__global__ __launch_bounds__(256, 2)
void av_kernel(const float* __restrict__ x, const float* __restrict__ attn,
               float* __restrict__ y) {
    __shared__ float As[32][130];
    __shared__ float Xs[32][65];

    const int t  = threadIdx.x;
    const int tx = t & 15;
    const int ty = t >> 4;
    const int n0 = blockIdx.x * 128;
    const int b  = blockIdx.y;
    const float* xb = x + (size_t)b * (CDIM * NDIM);
    const float* ab = attn + (size_t)b * NN;

    unsigned long long acc[4][4];
#pragma unroll
    for (int i = 0; i < 4; i++)
#pragma unroll
        for (int u = 0; u < 4; u++) acc[i][u] = 0ULL;

    for (int m0 = 0; m0 < NDIM; m0 += 32) {
        // As[j][r] = attn[n0+r][m0+j] : 4096 floats, coalesced 128B per warp
#pragma unroll
        for (int k = 0; k < 16; k++) {
            int idx = t + k * 256;
            int r = idx >> 5;
            int j = idx & 31;
            As[j][r] = ab[(size_t)(n0 + r) * NDIM + m0 + j];
        }
        // Xs[j][c] = x[c][m0+j] : 2048 floats
#pragma unroll
        for (int k = 0; k < 8; k++) {
            int idx = t + k * 256;
            int c = idx >> 5;
            int j = idx & 31;
            Xs[j][c] = xb[c * NDIM + m0 + j];
        }
        __syncthreads();

#pragma unroll
        for (int mm = 0; mm < 32; mm++) {
            unsigned long long a2[4];
#pragma unroll
            for (int i = 0; i < 4; i++)  // row pairs, 8B-aligned (130*4 % 8 == 0)
                a2[i] = *(const unsigned long long*)&As[mm][2 * ty + 32 * i];
#pragma unroll
            for (int u = 0; u < 4; u++) {
                float bv = Xs[mm][tx + 16 * u];
                unsigned long long b2 = pack2(bv, bv);
#pragma unroll
                for (int i = 0; i < 4; i++) ffma2(acc[i][u], a2[i], b2);
            }
        }
        __syncthreads();
    }

    // y output is [B][C][N]; f32x2 halves are consecutive n for a fixed c.
#pragma unroll
    for (int u = 0; u < 4; u++) {
        int c = tx + 16 * u;
#pragma unroll
        for (int i = 0; i < 4; i++) {
            float lo, hi;
            unpack2(lo, hi, acc[i][u]);
            int n = n0 + 2 * ty + 32 * i;
            *(float2*)&y[(size_t)b * (CDIM * NDIM) + (size_t)c * NDIM + n] =
                make_float2(lo, hi);
        }
    }
}

// ---------------------------------------------------------------------------
// Launch: d_in[0] = x (fp32, 2,097,152 elems).
// d_out = [ y (2,097,152 fp32) | attn (134,217,728 fp32) ] in tuple order.
// All launches graph-capturable; no sync, no allocation.
// ---------------------------------------------------------------------------
extern "C" void kernel_launch(void* const* d_in, const int* in_sizes, int n_in,
                              void* d_out, int out_size) {
    (void)in_sizes; (void)n_in; (void)out_size;
    const float* x = (const float*)d_in[0];
    float* out  = (float*)d_out;
    float* y    = out;
    float* attn = out + Y_ELEMS;

    dim3 g1(NDIM / 128, NDIM / 128, BATCH);   // (32, 32, 8)
    scores_kernel<<<g1, 256>>>(x, attn);

    dim3 g2(NDIM, BATCH);                     // (4096, 8)
    softmax_kernel<<<g2, 128>>>(attn);

    dim3 g3(NDIM / 128, BATCH);               // (32, 8) = one full wave @ occ 2
    av_kernel<<<g3, 256>>>(x, attn, y);
}